// round 14
// baseline (speedup 1.0000x reference)
#include <cuda_runtime.h>
#include <math.h>

typedef unsigned long long ull;

#define TT 2048
#define BB 64
#define II 128
#define HH 256
#define NBLK 128            /* 16 clusters x 8 CTAs */
#define CLUS 8
#define NTHR 512
#define HXS  68             /* gx-kernel x staging row stride */
#define WST  132            /* W_h slice row stride (128 cols + 4 pad) */

// ---- device scratch (static) ----
__device__ __align__(16) float g_gx[(size_t)TT * BB * HH * 4];   // [t][b][j][g]

// ---- helpers ----
__device__ __forceinline__ ull pk2(float v) {
    ull r; unsigned u = __float_as_uint(v);
    asm("mov.b64 %0, {%1, %1};" : "=l"(r) : "r"(u));
    return r;
}
__device__ __forceinline__ void fma2(ull& d, ull a, ull b) {
    asm("fma.rn.f32x2 %0, %1, %2, %0;" : "+l"(d) : "l"(a), "l"(b));
}
__device__ __forceinline__ ull add2(ull a, ull b) {
    ull r; asm("add.rn.f32x2 %0, %1, %2;" : "=l"(r) : "l"(a), "l"(b));
    return r;
}
__device__ __forceinline__ float tanh_ap(float x) {
    float y; asm("tanh.approx.f32 %0, %1;" : "=f"(y) : "f"(x));
    return y;
}
__device__ __forceinline__ float sig_ap(float x) {
    return fmaf(0.5f, tanh_ap(0.5f * x), 0.5f);
}
__device__ __forceinline__ unsigned smem_u32(const void* p) {
    unsigned a;
    asm("{ .reg .u64 t; cvta.to.shared.u64 t, %1; cvt.u32.u64 %0, t; }"
        : "=r"(a) : "l"(p));
    return a;
}
__device__ __forceinline__ unsigned mapa_rank(unsigned laddr, unsigned rank) {
    unsigned r;
    asm("mapa.shared::cluster.u32 %0, %1, %2;" : "=r"(r) : "r"(laddr), "r"(rank));
    return r;
}
__device__ __forceinline__ void mbar_wait(unsigned mb, unsigned par) {
    asm volatile(
        "{\n\t.reg .pred p;\n\t"
        "WAIT_%=:\n\t"
        "mbarrier.try_wait.parity.acquire.cluster.shared::cta.b64 p, [%0], %1, 0x989680;\n\t"
        "@p bra.uni DONE_%=;\n\t"
        "bra.uni WAIT_%=;\n\t"
        "DONE_%=:\n\t}"
        :: "r"(mb), "r"(par) : "memory");
}
#define CLUSTER_ARRIVE() asm volatile("barrier.cluster.arrive.aligned;" ::: "memory")
#define CLUSTER_WAIT()   asm volatile("barrier.cluster.wait.aligned;" ::: "memory")

// ============================================================
// Kernel 1: precompute gx[t][b][j][g] = (x_t . W_x), transpose fused.
// ============================================================
#define GX_XS 0
#define GX_WS (II * HXS)
#define GX_SMEM_FLOATS (GX_WS + II * 128)
#define GX_SMEM_BYTES  (GX_SMEM_FLOATS * 4)

__global__ void __launch_bounds__(512) gx_kernel(const float* __restrict__ x,
                                                 const float* __restrict__ Wx)
{
    extern __shared__ float sm[];
    float* xs  = sm + GX_XS;    // xs[i*68 + b]
    float* ws2 = sm + GX_WS;    // ws2[k*128 + hl*4 + g]

    const int t    = blockIdx.x;
    const int cb   = blockIdx.y;
    const int tid  = threadIdx.x;
    const int lane = tid & 31;
    const int bq   = tid >> 5;

    #pragma unroll
    for (int jj = 0; jj < 16; ++jj) {
        int idx = tid + jj * 512;
        int b = idx >> 7, i = idx & 127;
        xs[i * HXS + b] = __ldg(x + ((size_t)b * TT + t) * II + i);
    }
    #pragma unroll
    for (int jj = 0; jj < 32; ++jj) {
        int idx = tid + jj * 512;
        int k = idx >> 7, rem = idx & 127;
        int g = rem >> 5, hl = rem & 31;
        ws2[k * 128 + hl * 4 + g] = __ldg(Wx + ((size_t)g * II + k) * HH + (cb << 5) + hl);
    }
    __syncthreads();

    ull acc2[8];
    #pragma unroll
    for (int i = 0; i < 8; ++i) acc2[i] = 0ull;

    const float* xp = xs + (bq << 2);
    const float* wp = ws2 + (lane << 2);
    #pragma unroll 4
    for (int k = 0; k < II; ++k) {
        float4 hv = *(const float4*)(xp + k * HXS);
        ulonglong2 wv = *(const ulonglong2*)(wp + k * 128);
        ull h0 = pk2(hv.x), h1 = pk2(hv.y), h2 = pk2(hv.z), h3 = pk2(hv.w);
        fma2(acc2[0], h0, wv.x); fma2(acc2[1], h0, wv.y);
        fma2(acc2[2], h1, wv.x); fma2(acc2[3], h1, wv.y);
        fma2(acc2[4], h2, wv.x); fma2(acc2[5], h2, wv.y);
        fma2(acc2[6], h3, wv.x); fma2(acc2[7], h3, wv.y);
    }

    #pragma unroll
    for (int r = 0; r < 4; ++r) {
        int b = (bq << 2) + r;
        ulonglong2 v; v.x = acc2[r * 2]; v.y = acc2[r * 2 + 1];
        *(ulonglong2*)(g_gx + (((size_t)t * BB + b) * HH + (cb << 5) + lane) * 4) = v;
    }
}

// ============================================================
// Kernel 2: clustered LSTM, TWO independent recurrence chains per cluster.
// 16 clusters x 8 CTAs; cluster cid owns batches 4cid..4cid+3.
// Chain c (warps 8c..8c+7) owns batches {4cid+2c, 4cid+2c+1} with its own
// hb slab + mbarriers; chains never synchronize with each other, so one
// chain's compute hides the other's DSMEM/mbarrier latency.
// CTA rank r owns j in [32r, 32r+32). Warp wc (0..7 in chain): cols
// 16wc..16wc+15, both chain batches. Lane: k-slice {lane+32u, u<8}.
// acc2[b*8+p] = (batch b, col-pair p). Butterfly n=16..2 + xor1 unpack
// -> lane l holds output (b=l>>4, col=16wc+(l&15)).
// h exchange: st.async -> target's mbar, half-group split (ranks 0-3/4-7).
// SMEM: ws[256][132] @0 (shared by both chains),
//       hb[2 chains][2 bufs][256 j][2 b] @33792, mbar[2][2][2] static.
// ============================================================
#define SM_HB (HH * WST)
#define SMEM_FLOATS (SM_HB + 2 * 2 * HH * 2)
#define SMEM_BYTES  (SMEM_FLOATS * 4)
#define TXH 1024u   /* bytes per half-group per chain: 128 j x 2 b floats */

__global__ void __launch_bounds__(NTHR, 1) __cluster_dims__(CLUS, 1, 1)
lstm_kernel(const float* __restrict__ Wh, const float* __restrict__ bias,
            float* __restrict__ out)
{
    extern __shared__ float sm[];
    __shared__ __align__(8) ull mbar[8];   // [chain][buf][halfgroup]
    float* ws = sm;
    float* hb = sm + SM_HB;

    const int tid  = threadIdx.x;
    const int w    = tid >> 5;
    const int lane = tid & 31;
    const int wc   = w & 7;           // warp id within chain
    const int ch   = w >> 3;          // chain 0 / 1
    unsigned rank;
    asm("mov.u32 %0, %%cluster_ctarank;" : "=r"(rank));
    const int cid = blockIdx.x >> 3;

    // one-time: W_h slice ws[k*132 + jl*4 + g] = Wh[g][k][32r + jl]
    for (int idx = tid; idx < HH * 128; idx += NTHR) {
        int k = idx >> 7, rem = idx & 127;
        int g = rem >> 5, jl = rem & 31;
        ws[k * WST + jl * 4 + g] =
            __ldg(Wh + ((size_t)g * HH + k) * HH + (rank << 5) + jl);
    }

    const unsigned mb_u = smem_u32(mbar);
    if (tid == 0) {
        #pragma unroll
        for (int i = 0; i < 8; ++i)
            asm volatile("mbarrier.init.shared.b64 [%0], 1;"
                         :: "r"(mb_u + (i << 3)) : "memory");
    }
    __syncthreads();
    CLUSTER_ARRIVE(); CLUSTER_WAIT();   // mbarrier inits visible before any st.async
    if (tid == 0) {                     // first-use expect_tx for all 8 mbars
        #pragma unroll
        for (int i = 0; i < 8; ++i)
            asm volatile("mbarrier.arrive.expect_tx.shared.b64 _, [%0], %1;"
                         :: "r"(mb_u + (i << 3)), "r"(TXH) : "memory");
    }

    const int  col  = (wc << 4) + (lane & 15);
    const int  b_l  = lane >> 4;                   // batch within chain
    const int  j    = (int)(rank << 5) + (col >> 2);
    const int  gg_  = col & 3;
    const int  bse  = lane & 28;
    const bool upd  = (lane & 3) == 0;
    const bool lead = (tid & 255) == 0;            // one re-arm thread per chain
    const float biasv = __ldg(bias + (size_t)gg_ * HH + j);
    const int  myb  = (cid << 2) + (ch << 1) + b_l;
    const float* gxp = g_gx + (((size_t)myb * HH + j) << 2) + gg_;

    // chain-local bases (floats / bytes)
    const unsigned hb_u   = smem_u32(hb);
    const float*  hb_ch   = hb + (ch << 10);                // 1024 floats per chain
    const unsigned chbyte = (unsigned)(ch << 12);           // 4096 B per chain
    unsigned rb[CLUS];
    #pragma unroll
    for (int r = 0; r < CLUS; ++r) rb[r] = mapa_rank(hb_u, (unsigned)r);
    // producer's mbar slot on targets: [ch][buf][rank>>2]
    const unsigned mbdelta = mb_u - hb_u + ((unsigned)ch << 5) + ((rank >> 2) << 3);
    const unsigned joff = chbyte + (unsigned)j * 8 + ((unsigned)b_l << 2);
    const unsigned mb_ch = mb_u + ((unsigned)ch << 5);

    float creg = 0.f;

    for (int t = 0; t < TT; ++t) {
        float gxv = __ldg(gxp + (size_t)t * (BB * HH * 4));  // issued before wait

        ull acc2[16];
        #pragma unroll
        for (int i = 0; i < 16; ++i) acc2[i] = 0ull;

        if (t > 0) {
            const unsigned par = ((unsigned)(t - 1) >> 1) & 1u;
            const unsigned mbb = mb_ch + ((unsigned)(t & 1) << 4);
            const float* hbr = hb_ch + ((t & 1) << 9);       // 512 floats per buf
            const float* wsw = ws + (wc << 4);

            // ---- half A: ranks 0-3 (k < 128) ----
            mbar_wait(mbb, par);
            if (lead)
                asm volatile("mbarrier.arrive.expect_tx.shared.b64 _, [%0], %1;"
                             :: "r"(mbb), "r"(TXH) : "memory");
            #pragma unroll
            for (int u = 0; u < 4; ++u) {
                const int k = lane + (u << 5);
                float2 hv = *(const float2*)(hbr + (k << 1));
                ulonglong2 w0 = *(const ulonglong2*)(wsw + k * WST);
                ulonglong2 w1 = *(const ulonglong2*)(wsw + k * WST + 4);
                ulonglong2 w2 = *(const ulonglong2*)(wsw + k * WST + 8);
                ulonglong2 w3 = *(const ulonglong2*)(wsw + k * WST + 12);
                ull h0 = pk2(hv.x), h1 = pk2(hv.y);
                fma2(acc2[0],  h0, w0.x); fma2(acc2[1],  h0, w0.y);
                fma2(acc2[2],  h0, w1.x); fma2(acc2[3],  h0, w1.y);
                fma2(acc2[4],  h0, w2.x); fma2(acc2[5],  h0, w2.y);
                fma2(acc2[6],  h0, w3.x); fma2(acc2[7],  h0, w3.y);
                fma2(acc2[8],  h1, w0.x); fma2(acc2[9],  h1, w0.y);
                fma2(acc2[10], h1, w1.x); fma2(acc2[11], h1, w1.y);
                fma2(acc2[12], h1, w2.x); fma2(acc2[13], h1, w2.y);
                fma2(acc2[14], h1, w3.x); fma2(acc2[15], h1, w3.y);
            }
            // ---- half B: ranks 4-7 (k >= 128) ----
            mbar_wait(mbb + 8, par);
            if (lead)
                asm volatile("mbarrier.arrive.expect_tx.shared.b64 _, [%0], %1;"
                             :: "r"(mbb + 8), "r"(TXH) : "memory");
            #pragma unroll
            for (int u = 4; u < 8; ++u) {
                const int k = lane + (u << 5);
                float2 hv = *(const float2*)(hbr + (k << 1));
                ulonglong2 w0 = *(const ulonglong2*)(wsw + k * WST);
                ulonglong2 w1 = *(const ulonglong2*)(wsw + k * WST + 4);
                ulonglong2 w2 = *(const ulonglong2*)(wsw + k * WST + 8);
                ulonglong2 w3 = *(const ulonglong2*)(wsw + k * WST + 12);
                ull h0 = pk2(hv.x), h1 = pk2(hv.y);
                fma2(acc2[0],  h0, w0.x); fma2(acc2[1],  h0, w0.y);
                fma2(acc2[2],  h0, w1.x); fma2(acc2[3],  h0, w1.y);
                fma2(acc2[4],  h0, w2.x); fma2(acc2[5],  h0, w2.y);
                fma2(acc2[6],  h0, w3.x); fma2(acc2[7],  h0, w3.y);
                fma2(acc2[8],  h1, w0.x); fma2(acc2[9],  h1, w0.y);
                fma2(acc2[10], h1, w1.x); fma2(acc2[11], h1, w1.y);
                fma2(acc2[12], h1, w2.x); fma2(acc2[13], h1, w2.y);
                fma2(acc2[14], h1, w3.x); fma2(acc2[15], h1, w3.y);
            }
        }

        // packed butterfly reduce-scatter: acc2 idx = (b<<3)|p; lane bit4 <- b,
        // bits 3..1 <- p, bit0 <- pair half. Lane l ends with output
        // (b = l>>4, col = 16wc + (l&15)).
        #pragma unroll
        for (int n = 16; n >= 2; n >>= 1) {
            const int m = n >> 1;
            #pragma unroll
            for (int s = 0; s < m; ++s) {
                ull lo = acc2[s], hi = acc2[s + m];
                ull send = (lane & n) ? lo : hi;
                ull keep = (lane & n) ? hi : lo;
                acc2[s] = add2(keep, __shfl_xor_sync(0xffffffffu, send, n));
            }
        }
        float pre;
        {
            unsigned u0, u1;
            asm("mov.b64 {%0, %1}, %2;" : "=r"(u0), "=r"(u1) : "l"(acc2[0]));
            float a0 = __uint_as_float(u0), a1 = __uint_as_float(u1);
            float send = (lane & 1) ? a0 : a1;
            float keep = (lane & 1) ? a1 : a0;
            pre = keep + __shfl_xor_sync(0xffffffffu, send, 1);
        }
        pre += gxv + biasv;

        // per-lane activation (gate gg_: 2 -> tanh, else sigmoid), THEN gather
        float av = (gg_ == 2) ? tanh_ap(pre) : sig_ap(pre);
        float fg = __shfl_sync(0xffffffffu, av, bse | 1);
        float gv = __shfl_sync(0xffffffffu, av, bse | 2);
        float og = __shfl_sync(0xffffffffu, av, bse | 3);
        float hv_out = 0.f;
        if (upd) {
            creg = fg * creg + av * gv;           // av = i-gate on upd lanes
            hv_out = og * tanh_ap(creg);
            if (t + 1 < TT) {
                // push h_t to all 8 CTAs; each store signals the TARGET's
                // mbar[ch][buf][my halfgroup]
                const unsigned boff = (unsigned)((t & 1) ^ 1);
                const unsigned off  = (boff << 11) + joff;     // buf stride 2048B
                const unsigned moff = mbdelta + (boff << 4);   // buf stride 16B
                const unsigned hbits = __float_as_uint(hv_out);
                #pragma unroll
                for (int r = 0; r < CLUS; ++r) {
                    asm volatile(
                        "st.async.shared::cluster.mbarrier::complete_tx::bytes.b32 [%0], %1, [%2];"
                        :: "r"(rb[r] + off), "r"(hbits), "r"(rb[r] + moff)
                        : "memory");
                }
            }
        }

        if (upd)            // off the inter-CTA critical path
            out[((size_t)myb * TT + t) * HH + j] = hv_out;
    }

    CLUSTER_ARRIVE(); CLUSTER_WAIT();   // no early exit while peers may store into us
}

// ============================================================
extern "C" void kernel_launch(void* const* d_in, const int* in_sizes, int n_in,
                              void* d_out, int out_size)
{
    const float* x  = (const float*)d_in[0];   // [B, T, I]
    const float* Wx = (const float*)d_in[1];   // [4, I, H]
    const float* Wh = (const float*)d_in[2];   // [4, H, H]
    const float* b  = (const float*)d_in[3];   // [4, H]
    float* out = (float*)d_out;                // [B, T, H]

    cudaFuncSetAttribute(gx_kernel,
                         cudaFuncAttributeMaxDynamicSharedMemorySize, GX_SMEM_BYTES);
    cudaFuncSetAttribute(lstm_kernel,
                         cudaFuncAttributeMaxDynamicSharedMemorySize, SMEM_BYTES);

    gx_kernel<<<dim3(TT, 8), 512, GX_SMEM_BYTES>>>(x, Wx);
    lstm_kernel<<<NBLK, NTHR, SMEM_BYTES>>>(Wh, b, out);
}

// round 15
// speedup vs baseline: 1.0090x; 1.0090x over previous
#include <cuda_runtime.h>
#include <math.h>

typedef unsigned long long ull;

#define TT 2048
#define BB 64
#define II 128
#define HH 256
#define NBLK 128            /* 16 clusters x 8 CTAs */
#define CLUS 8
#define NTHR 512
#define HXS  68             /* gx-kernel x staging row stride */
#define WST  132            /* W_h slice row stride (128 cols + 4 pad) */

// ---- device scratch (static) ----
__device__ __align__(16) float g_gx[(size_t)TT * BB * HH * 4];   // [t][b][j][g]

// ---- helpers ----
__device__ __forceinline__ ull pk2(float v) {
    ull r; unsigned u = __float_as_uint(v);
    asm("mov.b64 %0, {%1, %1};" : "=l"(r) : "r"(u));
    return r;
}
__device__ __forceinline__ void fma2(ull& d, ull a, ull b) {
    asm("fma.rn.f32x2 %0, %1, %2, %0;" : "+l"(d) : "l"(a), "l"(b));
}
__device__ __forceinline__ ull add2(ull a, ull b) {
    ull r; asm("add.rn.f32x2 %0, %1, %2;" : "=l"(r) : "l"(a), "l"(b));
    return r;
}
__device__ __forceinline__ float tanh_ap(float x) {
    float y; asm("tanh.approx.f32 %0, %1;" : "=f"(y) : "f"(x));
    return y;
}
__device__ __forceinline__ float sig_ap(float x) {
    return fmaf(0.5f, tanh_ap(0.5f * x), 0.5f);
}
__device__ __forceinline__ unsigned smem_u32(const void* p) {
    unsigned a;
    asm("{ .reg .u64 t; cvta.to.shared.u64 t, %1; cvt.u32.u64 %0, t; }"
        : "=r"(a) : "l"(p));
    return a;
}
__device__ __forceinline__ unsigned mapa_rank(unsigned laddr, unsigned rank) {
    unsigned r;
    asm("mapa.shared::cluster.u32 %0, %1, %2;" : "=r"(r) : "r"(laddr), "r"(rank));
    return r;
}
__device__ __forceinline__ void mbar_wait(unsigned mb, unsigned par) {
    asm volatile(
        "{\n\t.reg .pred p;\n\t"
        "WAIT_%=:\n\t"
        "mbarrier.try_wait.parity.acquire.cluster.shared::cta.b64 p, [%0], %1, 0x989680;\n\t"
        "@p bra.uni DONE_%=;\n\t"
        "bra.uni WAIT_%=;\n\t"
        "DONE_%=:\n\t}"
        :: "r"(mb), "r"(par) : "memory");
}
#define CLUSTER_ARRIVE() asm volatile("barrier.cluster.arrive.aligned;" ::: "memory")
#define CLUSTER_WAIT()   asm volatile("barrier.cluster.wait.aligned;" ::: "memory")

// ============================================================
// Kernel 1: precompute gx[t][b][j][g] = (x_t . W_x), transpose fused.
// grid (t=2048, cb=8): cb covers h-cols 32cb..32cb+31 (x 4 gates).
// ============================================================
#define GX_XS 0
#define GX_WS (II * HXS)
#define GX_SMEM_FLOATS (GX_WS + II * 128)
#define GX_SMEM_BYTES  (GX_SMEM_FLOATS * 4)

__global__ void __launch_bounds__(512) gx_kernel(const float* __restrict__ x,
                                                 const float* __restrict__ Wx)
{
    extern __shared__ float sm[];
    float* xs  = sm + GX_XS;    // xs[i*68 + b]
    float* ws2 = sm + GX_WS;    // ws2[k*128 + hl*4 + g]

    const int t    = blockIdx.x;
    const int cb   = blockIdx.y;
    const int tid  = threadIdx.x;
    const int lane = tid & 31;
    const int bq   = tid >> 5;

    #pragma unroll
    for (int jj = 0; jj < 16; ++jj) {
        int idx = tid + jj * 512;
        int b = idx >> 7, i = idx & 127;
        xs[i * HXS + b] = __ldg(x + ((size_t)b * TT + t) * II + i);
    }
    #pragma unroll
    for (int jj = 0; jj < 32; ++jj) {
        int idx = tid + jj * 512;
        int k = idx >> 7, rem = idx & 127;
        int g = rem >> 5, hl = rem & 31;
        ws2[k * 128 + hl * 4 + g] = __ldg(Wx + ((size_t)g * II + k) * HH + (cb << 5) + hl);
    }
    __syncthreads();

    ull acc2[8];
    #pragma unroll
    for (int i = 0; i < 8; ++i) acc2[i] = 0ull;

    const float* xp = xs + (bq << 2);
    const float* wp = ws2 + (lane << 2);
    #pragma unroll 4
    for (int k = 0; k < II; ++k) {
        float4 hv = *(const float4*)(xp + k * HXS);
        ulonglong2 wv = *(const ulonglong2*)(wp + k * 128);
        ull h0 = pk2(hv.x), h1 = pk2(hv.y), h2 = pk2(hv.z), h3 = pk2(hv.w);
        fma2(acc2[0], h0, wv.x); fma2(acc2[1], h0, wv.y);
        fma2(acc2[2], h1, wv.x); fma2(acc2[3], h1, wv.y);
        fma2(acc2[4], h2, wv.x); fma2(acc2[5], h2, wv.y);
        fma2(acc2[6], h3, wv.x); fma2(acc2[7], h3, wv.y);
    }

    #pragma unroll
    for (int r = 0; r < 4; ++r) {
        int b = (bq << 2) + r;
        ulonglong2 v; v.x = acc2[r * 2]; v.y = acc2[r * 2 + 1];
        *(ulonglong2*)(g_gx + (((size_t)t * BB + b) * HH + (cb << 5) + lane) * 4) = v;
    }
}

// ============================================================
// Kernel 2: clustered LSTM (R13 structure), coarse-grained publish.
// 16 clusters x 8 CTAs; cluster cid owns batches 4cid..4cid+3.
// CTA rank r owns j in [32r, 32r+32). Warp w: cols 8w..8w+7, all 4
// batches. Lane: k-slice {lane+32u}. Half-group mbarriers (ranks 0-3/4-7)
// overlap delivery with the first 4 FMA u-iters.
// Publish: each warp's 8 h-outputs = 2 contiguous float4 rows in hb
// (j*16, b*4). Gather via 4 shfls -> lanes 0-1 push st.async.v4.b32
// (16B) to 8 targets: 256 stores/signals per CTA/step instead of 1024.
// SMEM: ws[256][132] @0, hb[2][256][4] @33792, mbar[2][2] static.
// ============================================================
#define SM_HB (HH * WST)
#define SMEM_FLOATS (SM_HB + 2 * HH * 4)
#define SMEM_BYTES  (SMEM_FLOATS * 4)
#define TXH 2048u   /* bytes per half-group: ranks r..r+3 = 512 floats */

__global__ void __launch_bounds__(NTHR, 1) __cluster_dims__(CLUS, 1, 1)
lstm_kernel(const float* __restrict__ Wh, const float* __restrict__ bias,
            float* __restrict__ out)
{
    extern __shared__ float sm[];
    __shared__ __align__(8) ull mbar[4];   // [buf][halfgroup]
    float* ws = sm;
    float* hb = sm + SM_HB;

    const int tid  = threadIdx.x;
    const int w    = tid >> 5;
    const int lane = tid & 31;
    unsigned rank;
    asm("mov.u32 %0, %%cluster_ctarank;" : "=r"(rank));
    const int cid = blockIdx.x >> 3;

    // one-time: W_h slice ws[k*132 + jl*4 + g] = Wh[g][k][32r + jl]
    for (int idx = tid; idx < HH * 128; idx += NTHR) {
        int k = idx >> 7, rem = idx & 127;
        int g = rem >> 5, jl = rem & 31;
        ws[k * WST + jl * 4 + g] =
            __ldg(Wh + ((size_t)g * HH + k) * HH + (rank << 5) + jl);
    }

    const unsigned mb_u = smem_u32(mbar);
    if (tid == 0) {
        #pragma unroll
        for (int i = 0; i < 4; ++i)
            asm volatile("mbarrier.init.shared.b64 [%0], 1;"
                         :: "r"(mb_u + (i << 3)) : "memory");
    }
    __syncthreads();
    CLUSTER_ARRIVE(); CLUSTER_WAIT();   // mbarrier inits visible before any st.async
    if (tid == 0) {                     // first-use expect_tx for all 4 mbars
        #pragma unroll
        for (int i = 0; i < 4; ++i)
            asm volatile("mbarrier.arrive.expect_tx.shared.b64 _, [%0], %1;"
                         :: "r"(mb_u + (i << 3)), "r"(TXH) : "memory");
    }

    const int  col  = (w << 3) + (lane & 7);
    const int  b_l  = lane >> 3;
    const int  j    = (int)(rank << 5) + (col >> 2);
    const int  gg_  = col & 3;
    const int  bse  = lane & 28;
    const bool upd  = (lane & 3) == 0;
    const float biasv = __ldg(bias + (size_t)gg_ * HH + j);
    const int  myb  = (cid << 2) + b_l;
    const float* gxp = g_gx + (((size_t)myb * HH + j) << 2) + gg_;

    // hoisted: remote hb bases; this CTA's half-group = rank>>2
    const unsigned hb_u = smem_u32(hb);
    unsigned rb[CLUS];
    #pragma unroll
    for (int r = 0; r < CLUS; ++r) rb[r] = mapa_rank(hb_u, (unsigned)r);
    const unsigned mbdelta = mb_u - hb_u + ((rank >> 2) << 3);  // +grp slot
    // pusher lane (0 or 1) owns j_p = 32*rank + 2w + lane; 16B row at j_p*16
    const unsigned push_off = ((rank << 5) + ((unsigned)w << 1) + (unsigned)(lane & 1)) << 4;

    float creg = 0.f;

    for (int t = 0; t < TT; ++t) {
        float gxv = __ldg(gxp + (size_t)t * (BB * HH * 4));  // issued before wait

        ull acc2[16];
        #pragma unroll
        for (int i = 0; i < 16; ++i) acc2[i] = 0ull;

        if (t > 0) {
            const unsigned par = ((unsigned)(t - 1) >> 1) & 1u;
            const unsigned mbb = mb_u + ((unsigned)(t & 1) << 4);
            const float* hbr = hb + ((t & 1) << 10);
            const float* wsw = ws + (w << 3);

            // ---- half A: ranks 0-3 (k < 128) ----
            mbar_wait(mbb, par);
            if (tid == 0)
                asm volatile("mbarrier.arrive.expect_tx.shared.b64 _, [%0], %1;"
                             :: "r"(mbb), "r"(TXH) : "memory");
            #pragma unroll
            for (int u = 0; u < 4; ++u) {
                const int k = lane + (u << 5);
                float4 hv = *(const float4*)(hbr + (k << 2));
                ulonglong2 w0 = *(const ulonglong2*)(wsw + k * WST);
                ulonglong2 w1 = *(const ulonglong2*)(wsw + k * WST + 4);
                ull h0 = pk2(hv.x), h1 = pk2(hv.y), h2 = pk2(hv.z), h3 = pk2(hv.w);
                fma2(acc2[0],  h0, w0.x); fma2(acc2[1],  h0, w0.y);
                fma2(acc2[2],  h0, w1.x); fma2(acc2[3],  h0, w1.y);
                fma2(acc2[4],  h1, w0.x); fma2(acc2[5],  h1, w0.y);
                fma2(acc2[6],  h1, w1.x); fma2(acc2[7],  h1, w1.y);
                fma2(acc2[8],  h2, w0.x); fma2(acc2[9],  h2, w0.y);
                fma2(acc2[10], h2, w1.x); fma2(acc2[11], h2, w1.y);
                fma2(acc2[12], h3, w0.x); fma2(acc2[13], h3, w0.y);
                fma2(acc2[14], h3, w1.x); fma2(acc2[15], h3, w1.y);
            }
            // ---- half B: ranks 4-7 (k >= 128) ----
            mbar_wait(mbb + 8, par);
            if (tid == 0)
                asm volatile("mbarrier.arrive.expect_tx.shared.b64 _, [%0], %1;"
                             :: "r"(mbb + 8), "r"(TXH) : "memory");
            #pragma unroll
            for (int u = 4; u < 8; ++u) {
                const int k = lane + (u << 5);
                float4 hv = *(const float4*)(hbr + (k << 2));
                ulonglong2 w0 = *(const ulonglong2*)(wsw + k * WST);
                ulonglong2 w1 = *(const ulonglong2*)(wsw + k * WST + 4);
                ull h0 = pk2(hv.x), h1 = pk2(hv.y), h2 = pk2(hv.z), h3 = pk2(hv.w);
                fma2(acc2[0],  h0, w0.x); fma2(acc2[1],  h0, w0.y);
                fma2(acc2[2],  h0, w1.x); fma2(acc2[3],  h0, w1.y);
                fma2(acc2[4],  h1, w0.x); fma2(acc2[5],  h1, w0.y);
                fma2(acc2[6],  h1, w1.x); fma2(acc2[7],  h1, w1.y);
                fma2(acc2[8],  h2, w0.x); fma2(acc2[9],  h2, w0.y);
                fma2(acc2[10], h2, w1.x); fma2(acc2[11], h2, w1.y);
                fma2(acc2[12], h3, w0.x); fma2(acc2[13], h3, w0.y);
                fma2(acc2[14], h3, w1.x); fma2(acc2[15], h3, w1.y);
            }
        }

        // packed butterfly reduce-scatter: lane l <- output (b=l>>3, col=8w+(l&7))
        #pragma unroll
        for (int n = 16; n >= 2; n >>= 1) {
            const int m = n >> 1;
            #pragma unroll
            for (int s = 0; s < m; ++s) {
                ull lo = acc2[s], hi = acc2[s + m];
                ull send = (lane & n) ? lo : hi;
                ull keep = (lane & n) ? hi : lo;
                acc2[s] = add2(keep, __shfl_xor_sync(0xffffffffu, send, n));
            }
        }
        float pre;
        {
            unsigned u0, u1;
            asm("mov.b64 {%0, %1}, %2;" : "=r"(u0), "=r"(u1) : "l"(acc2[0]));
            float a0 = __uint_as_float(u0), a1 = __uint_as_float(u1);
            float send = (lane & 1) ? a0 : a1;
            float keep = (lane & 1) ? a1 : a0;
            pre = keep + __shfl_xor_sync(0xffffffffu, send, 1);
        }
        pre += gxv + biasv;

        // per-lane activation (gate gg_: 2 -> tanh, else sigmoid), THEN gather
        float av = (gg_ == 2) ? tanh_ap(pre) : sig_ap(pre);
        float fg = __shfl_sync(0xffffffffu, av, bse | 1);
        float gv = __shfl_sync(0xffffffffu, av, bse | 2);
        float og = __shfl_sync(0xffffffffu, av, bse | 3);
        float hv_out = 0.f;
        if (upd) {
            creg = fg * creg + av * gv;           // av = i-gate on upd lanes
            hv_out = og * tanh_ap(creg);
        }

        // ---- coarse publish: warp's 8 outputs -> 2 float4 rows ----
        // value for (j parity p, batch b) lives at lane b*8 + p*4
        {
            const int p4 = (lane & 1) << 2;
            float r0 = __shfl_sync(0xffffffffu, hv_out, p4);
            float r1 = __shfl_sync(0xffffffffu, hv_out, p4 + 8);
            float r2 = __shfl_sync(0xffffffffu, hv_out, p4 + 16);
            float r3 = __shfl_sync(0xffffffffu, hv_out, p4 + 24);
            if (lane < 2 && t + 1 < TT) {
                const unsigned boff = (unsigned)((t & 1) ^ 1);
                const unsigned off  = (boff << 12) + push_off;
                const unsigned moff = mbdelta + (boff << 4);
                #pragma unroll
                for (int r = 0; r < CLUS; ++r) {
                    asm volatile(
                        "st.async.shared::cluster.mbarrier::complete_tx::bytes.v4.b32 "
                        "[%0], {%1, %2, %3, %4}, [%5];"
                        :: "r"(rb[r] + off), "f"(r0), "f"(r1), "f"(r2), "f"(r3),
                           "r"(rb[r] + moff)
                        : "memory");
                }
            }
        }

        if (upd)            // off the inter-CTA critical path
            out[((size_t)myb * TT + t) * HH + j] = hv_out;
    }

    CLUSTER_ARRIVE(); CLUSTER_WAIT();   // no early exit while peers may store into us
}

// ============================================================
extern "C" void kernel_launch(void* const* d_in, const int* in_sizes, int n_in,
                              void* d_out, int out_size)
{
    const float* x  = (const float*)d_in[0];   // [B, T, I]
    const float* Wx = (const float*)d_in[1];   // [4, I, H]
    const float* Wh = (const float*)d_in[2];   // [4, H, H]
    const float* b  = (const float*)d_in[3];   // [4, H]
    float* out = (float*)d_out;                // [B, T, H]

    cudaFuncSetAttribute(gx_kernel,
                         cudaFuncAttributeMaxDynamicSharedMemorySize, GX_SMEM_BYTES);
    cudaFuncSetAttribute(lstm_kernel,
                         cudaFuncAttributeMaxDynamicSharedMemorySize, SMEM_BYTES);

    gx_kernel<<<dim3(TT, 8), 512, GX_SMEM_BYTES>>>(x, Wx);
    lstm_kernel<<<NBLK, NTHR, SMEM_BYTES>>>(Wh, b, out);
}

// round 16
// speedup vs baseline: 1.1252x; 1.1151x over previous
#include <cuda_runtime.h>
#include <math.h>

typedef unsigned long long ull;

#define TT 2048
#define BB 64
#define II 128
#define HH 256
#define NBLK 128            /* 16 clusters x 8 CTAs */
#define CLUS 8
#define NTHR 512
#define HXS  68             /* gx-kernel x staging row stride */
#define WST  132            /* W_h slice row stride (128 cols + 4 pad) */
#define TSTEP 8             /* timesteps per gx block (weights staged once) */

// ---- device scratch (static) ----
__device__ __align__(16) float g_gx[(size_t)TT * BB * HH * 4];   // [t][b][j][g]

// ---- helpers ----
__device__ __forceinline__ ull pk2(float v) {
    ull r; unsigned u = __float_as_uint(v);
    asm("mov.b64 %0, {%1, %1};" : "=l"(r) : "r"(u));
    return r;
}
__device__ __forceinline__ void fma2(ull& d, ull a, ull b) {
    asm("fma.rn.f32x2 %0, %1, %2, %0;" : "+l"(d) : "l"(a), "l"(b));
}
__device__ __forceinline__ ull add2(ull a, ull b) {
    ull r; asm("add.rn.f32x2 %0, %1, %2;" : "=l"(r) : "l"(a), "l"(b));
    return r;
}
__device__ __forceinline__ float tanh_ap(float x) {
    float y; asm("tanh.approx.f32 %0, %1;" : "=f"(y) : "f"(x));
    return y;
}
__device__ __forceinline__ float sig_ap(float x) {
    return fmaf(0.5f, tanh_ap(0.5f * x), 0.5f);
}
__device__ __forceinline__ unsigned smem_u32(const void* p) {
    unsigned a;
    asm("{ .reg .u64 t; cvta.to.shared.u64 t, %1; cvt.u32.u64 %0, t; }"
        : "=r"(a) : "l"(p));
    return a;
}
__device__ __forceinline__ unsigned mapa_rank(unsigned laddr, unsigned rank) {
    unsigned r;
    asm("mapa.shared::cluster.u32 %0, %1, %2;" : "=r"(r) : "r"(laddr), "r"(rank));
    return r;
}
__device__ __forceinline__ void mbar_wait(unsigned mb, unsigned par) {
    asm volatile(
        "{\n\t.reg .pred p;\n\t"
        "WAIT_%=:\n\t"
        "mbarrier.try_wait.parity.acquire.cluster.shared::cta.b64 p, [%0], %1, 0x989680;\n\t"
        "@p bra.uni DONE_%=;\n\t"
        "bra.uni WAIT_%=;\n\t"
        "DONE_%=:\n\t}"
        :: "r"(mb), "r"(par) : "memory");
}
#define CLUSTER_ARRIVE() asm volatile("barrier.cluster.arrive.aligned;" ::: "memory")
#define CLUSTER_WAIT()   asm volatile("barrier.cluster.wait.aligned;" ::: "memory")

// ============================================================
// Kernel 1: precompute gx[t][b][j][g] = (x_t . W_x), transpose fused.
// grid (TT/TSTEP=256, cb=8). Weight slice staged ONCE per block and
// reused across TSTEP=8 timesteps (was: re-staged every t).
// ============================================================
#define GX_XS 0
#define GX_WS (II * HXS)
#define GX_SMEM_FLOATS (GX_WS + II * 128)
#define GX_SMEM_BYTES  (GX_SMEM_FLOATS * 4)

__global__ void __launch_bounds__(512) gx_kernel(const float* __restrict__ x,
                                                 const float* __restrict__ Wx)
{
    extern __shared__ float sm[];
    float* xs  = sm + GX_XS;    // xs[i*68 + b]
    float* ws2 = sm + GX_WS;    // ws2[k*128 + hl*4 + g]

    const int t0   = blockIdx.x * TSTEP;
    const int cb   = blockIdx.y;
    const int tid  = threadIdx.x;
    const int lane = tid & 31;
    const int bq   = tid >> 5;

    // ---- weight slice: staged once, reused for all TSTEP timesteps ----
    #pragma unroll
    for (int jj = 0; jj < 32; ++jj) {
        int idx = tid + jj * 512;
        int k = idx >> 7, rem = idx & 127;
        int g = rem >> 5, hl = rem & 31;
        ws2[k * 128 + hl * 4 + g] = __ldg(Wx + ((size_t)g * II + k) * HH + (cb << 5) + hl);
    }

    const float* xp = xs + (bq << 2);
    const float* wp = ws2 + (lane << 2);

    for (int tt = 0; tt < TSTEP; ++tt) {
        const int t = t0 + tt;

        __syncthreads();   // previous iteration's reads done before overwrite
        #pragma unroll
        for (int jj = 0; jj < 16; ++jj) {
            int idx = tid + jj * 512;
            int b = idx >> 7, i = idx & 127;
            xs[i * HXS + b] = __ldg(x + ((size_t)b * TT + t) * II + i);
        }
        __syncthreads();

        ull acc2[8];
        #pragma unroll
        for (int i = 0; i < 8; ++i) acc2[i] = 0ull;

        #pragma unroll 4
        for (int k = 0; k < II; ++k) {
            float4 hv = *(const float4*)(xp + k * HXS);
            ulonglong2 wv = *(const ulonglong2*)(wp + k * 128);
            ull h0 = pk2(hv.x), h1 = pk2(hv.y), h2 = pk2(hv.z), h3 = pk2(hv.w);
            fma2(acc2[0], h0, wv.x); fma2(acc2[1], h0, wv.y);
            fma2(acc2[2], h1, wv.x); fma2(acc2[3], h1, wv.y);
            fma2(acc2[4], h2, wv.x); fma2(acc2[5], h2, wv.y);
            fma2(acc2[6], h3, wv.x); fma2(acc2[7], h3, wv.y);
        }

        // thread covers j = 32cb + lane, gates 0..3, batches 4bq..4bq+3
        #pragma unroll
        for (int r = 0; r < 4; ++r) {
            int b = (bq << 2) + r;
            ulonglong2 v; v.x = acc2[r * 2]; v.y = acc2[r * 2 + 1];
            *(ulonglong2*)(g_gx + (((size_t)t * BB + b) * HH + (cb << 5) + lane) * 4) = v;
        }
    }
}

// ============================================================
// Kernel 2: clustered LSTM (exact R13 — best known).
// 16 clusters x 8 CTAs; cluster cid owns batches 4cid..4cid+3.
// CTA rank r owns j in [32r, 32r+32). Warp w: cols 8w..8w+7, all 4
// batches. Lane: k-slice {lane+32u}. Half-group mbarriers (ranks 0-3/4-7)
// overlap DSMEM delivery with the first 4 FMA u-iters. Per-lane gate
// activation before the gather. st.async per-element publish.
// SMEM: ws[256][132] @0, hb[2][256][4] @33792, mbar[2][2] static.
// ============================================================
#define SM_HB (HH * WST)
#define SMEM_FLOATS (SM_HB + 2 * HH * 4)
#define SMEM_BYTES  (SMEM_FLOATS * 4)
#define TXH 2048u   /* bytes per half-group: ranks r..r+3 = 512 floats */

__global__ void __launch_bounds__(NTHR, 1) __cluster_dims__(CLUS, 1, 1)
lstm_kernel(const float* __restrict__ Wh, const float* __restrict__ bias,
            float* __restrict__ out)
{
    extern __shared__ float sm[];
    __shared__ __align__(8) ull mbar[4];   // [buf][halfgroup]
    float* ws = sm;
    float* hb = sm + SM_HB;

    const int tid  = threadIdx.x;
    const int w    = tid >> 5;
    const int lane = tid & 31;
    unsigned rank;
    asm("mov.u32 %0, %%cluster_ctarank;" : "=r"(rank));
    const int cid = blockIdx.x >> 3;

    // one-time: W_h slice ws[k*132 + jl*4 + g] = Wh[g][k][32r + jl]
    for (int idx = tid; idx < HH * 128; idx += NTHR) {
        int k = idx >> 7, rem = idx & 127;
        int g = rem >> 5, jl = rem & 31;
        ws[k * WST + jl * 4 + g] =
            __ldg(Wh + ((size_t)g * HH + k) * HH + (rank << 5) + jl);
    }

    const unsigned mb_u = smem_u32(mbar);
    if (tid == 0) {
        #pragma unroll
        for (int i = 0; i < 4; ++i)
            asm volatile("mbarrier.init.shared.b64 [%0], 1;"
                         :: "r"(mb_u + (i << 3)) : "memory");
    }
    __syncthreads();
    CLUSTER_ARRIVE(); CLUSTER_WAIT();   // mbarrier inits visible before any st.async
    if (tid == 0) {                     // first-use expect_tx for all 4 mbars
        #pragma unroll
        for (int i = 0; i < 4; ++i)
            asm volatile("mbarrier.arrive.expect_tx.shared.b64 _, [%0], %1;"
                         :: "r"(mb_u + (i << 3)), "r"(TXH) : "memory");
    }

    const int  col  = (w << 3) + (lane & 7);
    const int  b_l  = lane >> 3;
    const int  j    = (int)(rank << 5) + (col >> 2);
    const int  gg_  = col & 3;
    const int  bse  = lane & 28;
    const bool upd  = (lane & 3) == 0;
    const float biasv = __ldg(bias + (size_t)gg_ * HH + j);
    const int  myb  = (cid << 2) + b_l;
    const float* gxp = g_gx + (((size_t)myb * HH + j) << 2) + gg_;

    // hoisted: remote hb bases; this CTA's half-group = rank>>2
    const unsigned hb_u = smem_u32(hb);
    unsigned rb[CLUS];
    #pragma unroll
    for (int r = 0; r < CLUS; ++r) rb[r] = mapa_rank(hb_u, (unsigned)r);
    const unsigned mbdelta = mb_u - hb_u + ((rank >> 2) << 3);  // +grp slot
    const unsigned joff = (unsigned)j * 16 + ((unsigned)b_l << 2);

    float creg = 0.f;

    for (int t = 0; t < TT; ++t) {
        float gxv = __ldg(gxp + (size_t)t * (BB * HH * 4));  // issued before wait

        ull acc2[16];
        #pragma unroll
        for (int i = 0; i < 16; ++i) acc2[i] = 0ull;

        if (t > 0) {
            const unsigned par = ((unsigned)(t - 1) >> 1) & 1u;
            const unsigned mbb = mb_u + ((unsigned)(t & 1) << 4);
            const float* hbr = hb + ((t & 1) << 10);
            const float* wsw = ws + (w << 3);

            // ---- half A: ranks 0-3 (k < 128) ----
            mbar_wait(mbb, par);
            if (tid == 0)
                asm volatile("mbarrier.arrive.expect_tx.shared.b64 _, [%0], %1;"
                             :: "r"(mbb), "r"(TXH) : "memory");
            #pragma unroll
            for (int u = 0; u < 4; ++u) {
                const int k = lane + (u << 5);
                float4 hv = *(const float4*)(hbr + (k << 2));
                ulonglong2 w0 = *(const ulonglong2*)(wsw + k * WST);
                ulonglong2 w1 = *(const ulonglong2*)(wsw + k * WST + 4);
                ull h0 = pk2(hv.x), h1 = pk2(hv.y), h2 = pk2(hv.z), h3 = pk2(hv.w);
                fma2(acc2[0],  h0, w0.x); fma2(acc2[1],  h0, w0.y);
                fma2(acc2[2],  h0, w1.x); fma2(acc2[3],  h0, w1.y);
                fma2(acc2[4],  h1, w0.x); fma2(acc2[5],  h1, w0.y);
                fma2(acc2[6],  h1, w1.x); fma2(acc2[7],  h1, w1.y);
                fma2(acc2[8],  h2, w0.x); fma2(acc2[9],  h2, w0.y);
                fma2(acc2[10], h2, w1.x); fma2(acc2[11], h2, w1.y);
                fma2(acc2[12], h3, w0.x); fma2(acc2[13], h3, w0.y);
                fma2(acc2[14], h3, w1.x); fma2(acc2[15], h3, w1.y);
            }
            // ---- half B: ranks 4-7 (k >= 128) ----
            mbar_wait(mbb + 8, par);
            if (tid == 0)
                asm volatile("mbarrier.arrive.expect_tx.shared.b64 _, [%0], %1;"
                             :: "r"(mbb + 8), "r"(TXH) : "memory");
            #pragma unroll
            for (int u = 4; u < 8; ++u) {
                const int k = lane + (u << 5);
                float4 hv = *(const float4*)(hbr + (k << 2));
                ulonglong2 w0 = *(const ulonglong2*)(wsw + k * WST);
                ulonglong2 w1 = *(const ulonglong2*)(wsw + k * WST + 4);
                ull h0 = pk2(hv.x), h1 = pk2(hv.y), h2 = pk2(hv.z), h3 = pk2(hv.w);
                fma2(acc2[0],  h0, w0.x); fma2(acc2[1],  h0, w0.y);
                fma2(acc2[2],  h0, w1.x); fma2(acc2[3],  h0, w1.y);
                fma2(acc2[4],  h1, w0.x); fma2(acc2[5],  h1, w0.y);
                fma2(acc2[6],  h1, w1.x); fma2(acc2[7],  h1, w1.y);
                fma2(acc2[8],  h2, w0.x); fma2(acc2[9],  h2, w0.y);
                fma2(acc2[10], h2, w1.x); fma2(acc2[11], h2, w1.y);
                fma2(acc2[12], h3, w0.x); fma2(acc2[13], h3, w0.y);
                fma2(acc2[14], h3, w1.x); fma2(acc2[15], h3, w1.y);
            }
        }

        // packed butterfly reduce-scatter: lane l <- output (b=l>>3, col=8w+(l&7))
        #pragma unroll
        for (int n = 16; n >= 2; n >>= 1) {
            const int m = n >> 1;
            #pragma unroll
            for (int s = 0; s < m; ++s) {
                ull lo = acc2[s], hi = acc2[s + m];
                ull send = (lane & n) ? lo : hi;
                ull keep = (lane & n) ? hi : lo;
                acc2[s] = add2(keep, __shfl_xor_sync(0xffffffffu, send, n));
            }
        }
        float pre;
        {
            unsigned u0, u1;
            asm("mov.b64 {%0, %1}, %2;" : "=r"(u0), "=r"(u1) : "l"(acc2[0]));
            float a0 = __uint_as_float(u0), a1 = __uint_as_float(u1);
            float send = (lane & 1) ? a0 : a1;
            float keep = (lane & 1) ? a1 : a0;
            pre = keep + __shfl_xor_sync(0xffffffffu, send, 1);
        }
        pre += gxv + biasv;

        // per-lane activation (gate gg_: 2 -> tanh, else sigmoid), THEN gather
        float av = (gg_ == 2) ? tanh_ap(pre) : sig_ap(pre);
        float fg = __shfl_sync(0xffffffffu, av, bse | 1);
        float gv = __shfl_sync(0xffffffffu, av, bse | 2);
        float og = __shfl_sync(0xffffffffu, av, bse | 3);
        float hv_out = 0.f;
        if (upd) {
            creg = fg * creg + av * gv;           // av = i-gate on upd lanes
            hv_out = og * tanh_ap(creg);
            if (t + 1 < TT) {
                // push h_t to all 8 CTAs; each store signals the TARGET's
                // mbar[buf][my halfgroup]
                const unsigned boff = (unsigned)((t & 1) ^ 1);
                const unsigned off  = (boff << 12) + joff;
                const unsigned moff = mbdelta + (boff << 4);
                const unsigned hbits = __float_as_uint(hv_out);
                #pragma unroll
                for (int r = 0; r < CLUS; ++r) {
                    asm volatile(
                        "st.async.shared::cluster.mbarrier::complete_tx::bytes.b32 [%0], %1, [%2];"
                        :: "r"(rb[r] + off), "r"(hbits), "r"(rb[r] + moff)
                        : "memory");
                }
            }
        }

        if (upd)            // off the inter-CTA critical path
            out[((size_t)myb * TT + t) * HH + j] = hv_out;
    }

    CLUSTER_ARRIVE(); CLUSTER_WAIT();   // no early exit while peers may store into us
}

// ============================================================
extern "C" void kernel_launch(void* const* d_in, const int* in_sizes, int n_in,
                              void* d_out, int out_size)
{
    const float* x  = (const float*)d_in[0];   // [B, T, I]
    const float* Wx = (const float*)d_in[1];   // [4, I, H]
    const float* Wh = (const float*)d_in[2];   // [4, H, H]
    const float* b  = (const float*)d_in[3];   // [4, H]
    float* out = (float*)d_out;                // [B, T, H]

    cudaFuncSetAttribute(gx_kernel,
                         cudaFuncAttributeMaxDynamicSharedMemorySize, GX_SMEM_BYTES);
    cudaFuncSetAttribute(lstm_kernel,
                         cudaFuncAttributeMaxDynamicSharedMemorySize, SMEM_BYTES);

    gx_kernel<<<dim3(TT / TSTEP, 8), 512, GX_SMEM_BYTES>>>(x, Wx);
    lstm_kernel<<<NBLK, NTHR, SMEM_BYTES>>>(Wh, b, out);
}